// round 1
// baseline (speedup 1.0000x reference)
#include <cuda_runtime.h>
#include <math_constants.h>
#include <math.h>

// Problem constants
#define S_LEN 2048
#define EMB   2048
#define NH    16
#define NKV   4
#define HD    128
#define FQKV  3072   // NH*HD + 2*NKV*HD

// Scratch (device globals: no allocations allowed)
__device__ float g_qkv[S_LEN * FQKV];   // ~25 MB
__device__ float g_ctx[S_LEN * EMB];    // ~17 MB

// ---------------------------------------------------------------------------
// SGEMM: C[m,n] = sum_k A[m,k] * B[n,k]   (A: MxK row-major, B: NxK row-major)
// 128x128 block tile, BK=16, 256 threads, 8x8 per-thread microtile.
// All dims assumed multiples of 128/16 (true for this problem).
// ---------------------------------------------------------------------------
__global__ __launch_bounds__(256) void sgemm_nt(const float* __restrict__ A,
                                                const float* __restrict__ B,
                                                float* __restrict__ C,
                                                int M, int N, int K)
{
    __shared__ float As[16][132];   // [k][m], padded
    __shared__ float Bs[16][132];   // [k][n], padded

    const int tid = threadIdx.x;
    const int tx  = tid & 15;
    const int ty  = tid >> 4;
    const int bm  = blockIdx.y * 128;
    const int bn  = blockIdx.x * 128;

    const int lrow = tid >> 2;          // 0..63
    const int lcol = (tid & 3) << 2;    // 0,4,8,12

    float acc[8][8];
#pragma unroll
    for (int i = 0; i < 8; i++)
#pragma unroll
        for (int j = 0; j < 8; j++) acc[i][j] = 0.f;

    for (int k0 = 0; k0 < K; k0 += 16) {
#pragma unroll
        for (int half = 0; half < 2; half++) {
            int m = lrow + half * 64;
            float4 va = *(const float4*)(A + (size_t)(bm + m) * K + k0 + lcol);
            As[lcol + 0][m] = va.x; As[lcol + 1][m] = va.y;
            As[lcol + 2][m] = va.z; As[lcol + 3][m] = va.w;
            float4 vb = *(const float4*)(B + (size_t)(bn + m) * K + k0 + lcol);
            Bs[lcol + 0][m] = vb.x; Bs[lcol + 1][m] = vb.y;
            Bs[lcol + 2][m] = vb.z; Bs[lcol + 3][m] = vb.w;
        }
        __syncthreads();

#pragma unroll
        for (int k = 0; k < 16; k++) {
            float a[8], b[8];
            *(float4*)(a)     = *(const float4*)(&As[k][ty * 4]);
            *(float4*)(a + 4) = *(const float4*)(&As[k][64 + ty * 4]);
            *(float4*)(b)     = *(const float4*)(&Bs[k][tx * 4]);
            *(float4*)(b + 4) = *(const float4*)(&Bs[k][64 + tx * 4]);
#pragma unroll
            for (int i = 0; i < 8; i++)
#pragma unroll
                for (int j = 0; j < 8; j++)
                    acc[i][j] = fmaf(a[i], b[j], acc[i][j]);
        }
        __syncthreads();
    }

#pragma unroll
    for (int i = 0; i < 8; i++) {
        int m = bm + ((i < 4) ? (ty * 4 + i) : (64 + ty * 4 + (i - 4)));
        float4 v0 = make_float4(acc[i][0], acc[i][1], acc[i][2], acc[i][3]);
        float4 v1 = make_float4(acc[i][4], acc[i][5], acc[i][6], acc[i][7]);
        *(float4*)(C + (size_t)m * N + bn + tx * 4)      = v0;
        *(float4*)(C + (size_t)m * N + bn + 64 + tx * 4) = v1;
    }
}

// ---------------------------------------------------------------------------
// RoPE applied in-place to Q (heads 0..15) and K (heads 16..19) inside g_qkv.
// rotate_half convention: out[i] = x[i]*cos - x[i+64]*sin ; out[i+64] = x[i+64]*cos + x[i]*sin
// ---------------------------------------------------------------------------
__global__ void rope_kernel()
{
    int s    = blockIdx.x;      // 0..2047
    int head = blockIdx.y;      // 0..19 : 16 q heads then 4 k heads
    int i    = threadIdx.x;     // 0..63

    size_t off = (size_t)s * FQKV +
                 ((head < NH) ? (size_t)head * HD
                              : (size_t)NH * HD + (size_t)(head - NH) * HD);
    float* base = g_qkv + off;

    // inv_freq = 10000^(-(2i)/128) = exp(-(2i/128) * ln(10000))
    float inv_freq = expf(-(float)(2 * i) * (9.210340371976184f / 128.f));
    float ang = (float)s * inv_freq;
    float c, sn;
    sincosf(ang, &sn, &c);

    float x1 = base[i];
    float x2 = base[i + 64];
    base[i]      = x1 * c - x2 * sn;
    base[i + 64] = x2 * c + x1 * sn;
}

// ---------------------------------------------------------------------------
// Flash attention, fp32, causal, GQA (4 q heads share 1 kv head).
// Block: 64 query rows of one head. 256 threads (16x16).
// Thread (ty,tx): S rows ty*4..+3 x cols tx*4..+3; O rows ty*4..+3 x
//   d-cols {tx*4..+3} U {64+tx*4..+3}.
// smem: Qt[128][64] (k-major), Kt[128][64], Vs[64][128], Ps[64][64] = 112KB.
// ---------------------------------------------------------------------------
__global__ __launch_bounds__(256) void flash_attn()
{
    extern __shared__ float sm[];
    float* Qt = sm;            // 8192
    float* Kt = sm + 8192;     // 8192
    float* Vs = sm + 16384;    // 8192
    float* Ps = sm + 24576;    // 4096

    const int tid = threadIdx.x;
    const int tx  = tid & 15;
    const int ty  = tid >> 4;
    const int h   = blockIdx.y;
    const int kvh = h >> 2;
    const int q0  = blockIdx.x * 64;
    const float scale = 0.08838834764831845f;  // 1/sqrt(128)

    const int lr = tid >> 2;         // 0..63
    const int lc = (tid & 3) << 2;   // 0,4,8,12

    // Load Q tile transposed: Qt[k][r]
#pragma unroll
    for (int c0 = lc; c0 < 128; c0 += 16) {
        float4 v = *(const float4*)(g_qkv + (size_t)(q0 + lr) * FQKV + h * HD + c0);
        Qt[(c0 + 0) * 64 + lr] = v.x; Qt[(c0 + 1) * 64 + lr] = v.y;
        Qt[(c0 + 2) * 64 + lr] = v.z; Qt[(c0 + 3) * 64 + lr] = v.w;
    }

    float m_i[4], l_i[4], o[4][8];
#pragma unroll
    for (int i = 0; i < 4; i++) {
        m_i[i] = -CUDART_INF_F;
        l_i[i] = 0.f;
#pragma unroll
        for (int j = 0; j < 8; j++) o[i][j] = 0.f;
    }

    const int ntiles = blockIdx.x + 1;   // causal: only tiles with keys <= queries
    for (int jt = 0; jt < ntiles; jt++) {
        const int k0 = jt * 64;

        // Load K transposed + V row-major for this tile
#pragma unroll
        for (int c0 = lc; c0 < 128; c0 += 16) {
            const float* kp = g_qkv + (size_t)(k0 + lr) * FQKV + NH * HD + kvh * HD + c0;
            float4 v = *(const float4*)kp;
            Kt[(c0 + 0) * 64 + lr] = v.x; Kt[(c0 + 1) * 64 + lr] = v.y;
            Kt[(c0 + 2) * 64 + lr] = v.z; Kt[(c0 + 3) * 64 + lr] = v.w;
            float4 w = *(const float4*)(kp + NKV * HD);
            *(float4*)(Vs + lr * 128 + c0) = w;
        }
        __syncthreads();

        // S = Q K^T  (4x4 per thread)
        float s[4][4];
#pragma unroll
        for (int i = 0; i < 4; i++)
#pragma unroll
            for (int j = 0; j < 4; j++) s[i][j] = 0.f;

#pragma unroll 4
        for (int k = 0; k < 128; k++) {
            float a[4], b[4];
            *(float4*)a = *(const float4*)(Qt + k * 64 + ty * 4);
            *(float4*)b = *(const float4*)(Kt + k * 64 + tx * 4);
#pragma unroll
            for (int i = 0; i < 4; i++)
#pragma unroll
                for (int j = 0; j < 4; j++)
                    s[i][j] = fmaf(a[i], b[j], s[i][j]);
        }

        // scale + causal mask
#pragma unroll
        for (int i = 0; i < 4; i++) {
            int r = q0 + ty * 4 + i;
#pragma unroll
            for (int j = 0; j < 4; j++) {
                int c = k0 + tx * 4 + j;
                s[i][j] = (c <= r) ? s[i][j] * scale : -CUDART_INF_F;
            }
        }

        // online softmax per row (reduce across the 16 tx lanes)
#pragma unroll
        for (int i = 0; i < 4; i++) {
            float mx = fmaxf(fmaxf(s[i][0], s[i][1]), fmaxf(s[i][2], s[i][3]));
#pragma unroll
            for (int off = 8; off >= 1; off >>= 1)
                mx = fmaxf(mx, __shfl_xor_sync(0xffffffffu, mx, off));
            float mnew  = fmaxf(m_i[i], mx);
            float alpha = expf(m_i[i] - mnew);
            float rs = 0.f;
#pragma unroll
            for (int j = 0; j < 4; j++) {
                s[i][j] = expf(s[i][j] - mnew);
                rs += s[i][j];
            }
#pragma unroll
            for (int off = 8; off >= 1; off >>= 1)
                rs += __shfl_xor_sync(0xffffffffu, rs, off);
            l_i[i] = l_i[i] * alpha + rs;
            m_i[i] = mnew;
#pragma unroll
            for (int j = 0; j < 8; j++) o[i][j] *= alpha;
            *(float4*)(Ps + (ty * 4 + i) * 64 + tx * 4) =
                make_float4(s[i][0], s[i][1], s[i][2], s[i][3]);
        }
        __syncthreads();

        // O += P @ V
#pragma unroll 2
        for (int j = 0; j < 64; j++) {
            float p[4];
#pragma unroll
            for (int i = 0; i < 4; i++) p[i] = Ps[(ty * 4 + i) * 64 + j];
            float4 v0 = *(const float4*)(Vs + j * 128 + tx * 4);
            float4 v1 = *(const float4*)(Vs + j * 128 + 64 + tx * 4);
#pragma unroll
            for (int i = 0; i < 4; i++) {
                o[i][0] = fmaf(p[i], v0.x, o[i][0]);
                o[i][1] = fmaf(p[i], v0.y, o[i][1]);
                o[i][2] = fmaf(p[i], v0.z, o[i][2]);
                o[i][3] = fmaf(p[i], v0.w, o[i][3]);
                o[i][4] = fmaf(p[i], v1.x, o[i][4]);
                o[i][5] = fmaf(p[i], v1.y, o[i][5]);
                o[i][6] = fmaf(p[i], v1.z, o[i][6]);
                o[i][7] = fmaf(p[i], v1.w, o[i][7]);
            }
        }
        __syncthreads();
    }

    // epilogue: normalize, write ctx[s, h*128 + d]
#pragma unroll
    for (int i = 0; i < 4; i++) {
        float inv = 1.f / l_i[i];
        int r = q0 + ty * 4 + i;
        float4 v0 = make_float4(o[i][0] * inv, o[i][1] * inv, o[i][2] * inv, o[i][3] * inv);
        float4 v1 = make_float4(o[i][4] * inv, o[i][5] * inv, o[i][6] * inv, o[i][7] * inv);
        *(float4*)(g_ctx + (size_t)r * EMB + h * HD + tx * 4)      = v0;
        *(float4*)(g_ctx + (size_t)r * EMB + h * HD + 64 + tx * 4) = v1;
    }
}

// ---------------------------------------------------------------------------
// Launch
// ---------------------------------------------------------------------------
extern "C" void kernel_launch(void* const* d_in, const int* in_sizes, int n_in,
                              void* d_out, int out_size)
{
    const float* x       = (const float*)d_in[0];
    const float* w_qkv   = (const float*)d_in[1];
    const float* w_dense = (const float*)d_in[2];
    float* out = (float*)d_out;

    float *qkv, *ctx;
    cudaGetSymbolAddress((void**)&qkv, g_qkv);
    cudaGetSymbolAddress((void**)&ctx, g_ctx);

    cudaFuncSetAttribute(flash_attn, cudaFuncAttributeMaxDynamicSharedMemorySize, 114688);

    // 1) qkv = x @ w_qkv^T
    sgemm_nt<<<dim3(FQKV / 128, S_LEN / 128), 256>>>(x, w_qkv, qkv, S_LEN, FQKV, EMB);
    // 2) RoPE in-place on q and k
    rope_kernel<<<dim3(S_LEN, NH + NKV), 64>>>();
    // 3) causal GQA flash attention -> ctx
    flash_attn<<<dim3(S_LEN / 64, NH), 256, 114688>>>();
    // 4) out = ctx @ w_dense^T
    sgemm_nt<<<dim3(EMB / 128, S_LEN / 128), 256>>>(ctx, w_dense, out, S_LEN, EMB, EMB);
}

// round 6
// speedup vs baseline: 2.9910x; 2.9910x over previous
#include <cuda_runtime.h>
#include <math_constants.h>
#include <math.h>
#include <cstdint>

// Problem constants
#define S_LEN 2048
#define EMB   2048
#define NH    16
#define NKV   4
#define HD    128
#define FQKV  3072   // NH*HD + 2*NKV*HD

// Scratch (device globals: no allocations allowed)
__device__ float g_qkv[S_LEN * FQKV];     // 25 MB
__device__ float g_ctx[S_LEN * EMB];      // 17 MB (tf32-rounded ctx)
__device__ float g_xr[S_LEN * EMB];       // 16 MB (tf32-rounded x)
__device__ float g_wqkvr[FQKV * EMB];     // 24 MB
__device__ float g_wdr[EMB * EMB];        // 16 MB

// ---------------------------------------------------------------------------
// Helpers (plain sm_100: legacy mma.sync tensor cores, NO tcgen05)
// ---------------------------------------------------------------------------
__device__ __forceinline__ uint32_t smem_u32(const void* p) {
    uint32_t a;
    asm("{ .reg .u64 t; cvta.to.shared.u64 t, %1; cvt.u32.u64 %0, t; }"
        : "=r"(a) : "l"(p));
    return a;
}

// round-to-nearest tf32 (kills truncation bias in mma)
__device__ __forceinline__ float tf32r(float x) {
    uint32_t u;
    asm("cvt.rna.tf32.f32 %0, %1;" : "=r"(u) : "f"(x));
    return __uint_as_float(u);
}

// D += A(16x8,row) * B(8x8,col)  tf32, f32 accum
__device__ __forceinline__ void mma8(float* c, const uint32_t* a,
                                     uint32_t b0, uint32_t b1) {
    asm volatile(
        "mma.sync.aligned.m16n8k8.row.col.f32.tf32.tf32.f32 "
        "{%0,%1,%2,%3}, {%4,%5,%6,%7}, {%8,%9}, {%0,%1,%2,%3};\n"
        : "+f"(c[0]), "+f"(c[1]), "+f"(c[2]), "+f"(c[3])
        : "r"(a[0]), "r"(a[1]), "r"(a[2]), "r"(a[3]), "r"(b0), "r"(b1));
}

// ldmatrix.x4 over a 16(row) x 8(f32 col) tile at (row0,col0), f32 row stride.
// r0=(t/4,t%4) r1=(+8,) r2=(,+4) r3=(+8,+4)  == tf32 A-fragment (and, with
// row=n (or n-transposed operand), two B-fragments).
__device__ __forceinline__ void ldm4(uint32_t* r, const float* base,
                                     int row0, int col0, int stride) {
    int t = threadIdx.x & 31;
    int rr = row0 + (t & 7) + (((t >> 3) & 1) << 3);
    int cc = col0 + ((t >> 4) << 2);
    uint32_t addr = smem_u32(base + rr * stride + cc);
    asm volatile("ldmatrix.sync.aligned.m8n8.x4.shared.b16 {%0,%1,%2,%3}, [%4];"
                 : "=r"(r[0]), "=r"(r[1]), "=r"(r[2]), "=r"(r[3]) : "r"(addr));
}

__device__ __forceinline__ void cpasync16(uint32_t dst, const float* src) {
    asm volatile("cp.async.cg.shared.global [%0], [%1], 16;" :: "r"(dst), "l"(src));
}

// ---------------------------------------------------------------------------
// tf32 pre-round: out[i] = round_tf32(in[i])
// ---------------------------------------------------------------------------
__global__ void round_tf32_kernel(const float* __restrict__ in,
                                  float* __restrict__ out, int n4) {
    int i = blockIdx.x * blockDim.x + threadIdx.x;
    for (; i < n4; i += gridDim.x * blockDim.x) {
        float4 v = ((const float4*)in)[i];
        v.x = tf32r(v.x); v.y = tf32r(v.y); v.z = tf32r(v.z); v.w = tf32r(v.w);
        ((float4*)out)[i] = v;
    }
}

// ---------------------------------------------------------------------------
// tf32 mma GEMM: C[m,n] = sum_k A[m,k]*B[n,k]; A,B tf32-pre-rounded fp32.
// 128x128 tile, BK=32, 256 thr (8 warps, warp-tile 64x32), 2-stage cp.async.
// smem stride 36 f32 (rows land in distinct bank quads for ldmatrix).
// ---------------------------------------------------------------------------
#define GST 36                      // padded f32 stride
#define GSTAGE (128 * GST)          // 4608 f32 per operand per stage
#define GEMM_SMEM (2 * 2 * GSTAGE * 4)   // 73728 B

__device__ __forceinline__ void gemm_issue(const float* __restrict__ A,
                                           const float* __restrict__ B,
                                           uint32_t sbase, int stage,
                                           int bm, int bn, int K, int k0, int tid) {
    uint32_t as = sbase + stage * (2 * GSTAGE * 4);
    uint32_t bs = as + GSTAGE * 4;
#pragma unroll
    for (int i = 0; i < 4; i++) {
        int idx = i * 256 + tid;      // 0..1023
        int row = idx >> 3;           // 0..127
        int g   = idx & 7;            // 16B granule
        uint32_t off = (uint32_t)(row * GST + g * 4) * 4;
        cpasync16(as + off, A + (size_t)(bm + row) * K + k0 + g * 4);
        cpasync16(bs + off, B + (size_t)(bn + row) * K + k0 + g * 4);
    }
    asm volatile("cp.async.commit_group;");
}

__global__ __launch_bounds__(256, 2) void gemm_mma(const float* __restrict__ A,
                                                   const float* __restrict__ B,
                                                   float* __restrict__ C,
                                                   int M, int N, int K) {
    extern __shared__ float sm[];
    const uint32_t sbase = smem_u32(sm);
    const int tid = threadIdx.x;
    const int lane = tid & 31;
    const int wid = tid >> 5;
    const int bm = blockIdx.y * 128;
    const int bn = blockIdx.x * 128;
    const int wm = (wid >> 2) * 64;
    const int wn = (wid & 3) * 32;

    float acc[4][4][4];
#pragma unroll
    for (int i = 0; i < 4; i++)
#pragma unroll
        for (int j = 0; j < 4; j++)
#pragma unroll
            for (int q = 0; q < 4; q++) acc[i][j][q] = 0.f;

    const int NC = K / 32;
    gemm_issue(A, B, sbase, 0, bm, bn, K, 0, tid);

    for (int c = 0; c < NC; c++) {
        if (c + 1 < NC) {
            gemm_issue(A, B, sbase, (c + 1) & 1, bm, bn, K, (c + 1) * 32, tid);
            asm volatile("cp.async.wait_group 1;");
        } else {
            asm volatile("cp.async.wait_group 0;");
        }
        __syncthreads();

        const float* As = sm + (c & 1) * 2 * GSTAGE;
        const float* Bs = As + GSTAGE;
#pragma unroll
        for (int kk = 0; kk < 4; kk++) {
            uint32_t a[4][4];
#pragma unroll
            for (int mf = 0; mf < 4; mf++)
                ldm4(a[mf], As, wm + 16 * mf, kk * 8, GST);
#pragma unroll
            for (int j = 0; j < 2; j++) {
                uint32_t b[4];
                ldm4(b, Bs, wn + 16 * j, kk * 8, GST);
#pragma unroll
                for (int mf = 0; mf < 4; mf++) {
                    mma8(acc[mf][2 * j],     a[mf], b[0], b[2]);
                    mma8(acc[mf][2 * j + 1], a[mf], b[1], b[3]);
                }
            }
        }
        __syncthreads();
    }

    // epilogue: c-frag (row t/4 [+8], cols 2*(t%4)+{0,1})
#pragma unroll
    for (int mf = 0; mf < 4; mf++) {
        int r0 = bm + wm + mf * 16 + (lane >> 2);
#pragma unroll
        for (int nf = 0; nf < 4; nf++) {
            int cc = bn + wn + nf * 8 + 2 * (lane & 3);
            *(float2*)(C + (size_t)r0 * N + cc) =
                make_float2(acc[mf][nf][0], acc[mf][nf][1]);
            *(float2*)(C + (size_t)(r0 + 8) * N + cc) =
                make_float2(acc[mf][nf][2], acc[mf][nf][3]);
        }
    }
}

// ---------------------------------------------------------------------------
// RoPE in-place on Q (heads 0..15) and K (heads 16..19) in g_qkv (fp32).
// ---------------------------------------------------------------------------
__global__ void rope_kernel() {
    int s    = blockIdx.x;
    int head = blockIdx.y;
    int i    = threadIdx.x;

    size_t off = (size_t)s * FQKV +
                 ((head < NH) ? (size_t)head * HD
                              : (size_t)NH * HD + (size_t)(head - NH) * HD);
    float* base = g_qkv + off;

    float inv_freq = expf(-(float)(2 * i) * (9.210340371976184f / 128.f));
    float ang = (float)s * inv_freq;
    float c, sn;
    sincosf(ang, &sn, &c);

    float x1 = base[i];
    float x2 = base[i + 64];
    base[i]      = x1 * c - x2 * sn;
    base[i + 64] = x2 * c + x1 * sn;
}

// ---------------------------------------------------------------------------
// Flash attention on mma.sync tf32. CTA: 128 q-rows, 8 warps (16 rows each),
// k-tile 64. smem: Qs[128x132], Ks[64x132], Vt[128x68] (d-major transposed),
// Ps[128x68]. Online softmax in c-fragment registers.
// ---------------------------------------------------------------------------
#define QS_OFF 0
#define KS_OFF (128 * 132)                 // 16896
#define VT_OFF (KS_OFF + 64 * 132)         // 25344
#define PS_OFF (VT_OFF + 128 * 68)         // 34048
#define ATT_SMEM ((PS_OFF + 128 * 68) * 4) // 171008 B

__global__ __launch_bounds__(256, 1) void flash_attn_mma() {
    extern __shared__ float sm[];
    float* Qs = sm + QS_OFF;
    float* Ks = sm + KS_OFF;
    float* Vt = sm + VT_OFF;
    float* Ps = sm + PS_OFF;

    const int tid = threadIdx.x;
    const int lane = tid & 31;
    const int w = tid >> 5;
    const int h = blockIdx.x;
    const int kvh = h >> 2;
    const int qt = (int)gridDim.y - 1 - (int)blockIdx.y;  // heavy first
    const int q0 = qt * 128;
    const float scale = 0.08838834764831845f;   // 1/sqrt(128)

    // Load Q (128x128), tf32-round into padded smem
#pragma unroll
    for (int i = 0; i < 16; i++) {
        int idx = i * 256 + tid;
        int row = idx >> 5;
        int c4  = (idx & 31) * 4;
        float4 v = *(const float4*)(g_qkv + (size_t)(q0 + row) * FQKV + h * HD + c4);
        v.x = tf32r(v.x); v.y = tf32r(v.y); v.z = tf32r(v.z); v.w = tf32r(v.w);
        *(float4*)(Qs + row * 132 + c4) = v;
    }

    float m0 = -CUDART_INF_F, m1 = -CUDART_INF_F, l0 = 0.f, l1 = 0.f;
    float o[16][4];
#pragma unroll
    for (int f = 0; f < 16; f++)
#pragma unroll
        for (int q = 0; q < 4; q++) o[f][q] = 0.f;

    const int nkt = 2 * (qt + 1);
    for (int kt = 0; kt < nkt; kt++) {
        const int k0 = kt * 64;

        // Load K (64x128) and V transposed (d-major)
#pragma unroll
        for (int i = 0; i < 8; i++) {
            int idx = i * 256 + tid;
            int row = idx >> 5;
            int c4  = (idx & 31) * 4;
            const float* kp = g_qkv + (size_t)(k0 + row) * FQKV + NH * HD + kvh * HD + c4;
            float4 v = *(const float4*)kp;
            v.x = tf32r(v.x); v.y = tf32r(v.y); v.z = tf32r(v.z); v.w = tf32r(v.w);
            *(float4*)(Ks + row * 132 + c4) = v;
            float4 u = *(const float4*)(kp + NKV * HD);
            Vt[(c4 + 0) * 68 + row] = tf32r(u.x);
            Vt[(c4 + 1) * 68 + row] = tf32r(u.y);
            Vt[(c4 + 2) * 68 + row] = tf32r(u.z);
            Vt[(c4 + 3) * 68 + row] = tf32r(u.w);
        }
        __syncthreads();

        // S = Q K^T : per warp 16x64
        float s[8][4];
#pragma unroll
        for (int f = 0; f < 8; f++)
#pragma unroll
            for (int q = 0; q < 4; q++) s[f][q] = 0.f;

#pragma unroll 4
        for (int kk = 0; kk < 16; kk++) {
            uint32_t a[4];
            ldm4(a, Qs, 16 * w, kk * 8, 132);
#pragma unroll
            for (int j = 0; j < 4; j++) {
                uint32_t b[4];
                ldm4(b, Ks, 16 * j, kk * 8, 132);
                mma8(s[2 * j],     a, b[0], b[2]);
                mma8(s[2 * j + 1], a, b[1], b[3]);
            }
        }

        // mask + scale (frag f covers cols 8f..8f+7; rows t/4, t/4+8)
        const int r0g = q0 + 16 * w + (lane >> 2);
        const int r1g = r0g + 8;
#pragma unroll
        for (int f = 0; f < 8; f++) {
            int c0g = k0 + 8 * f + 2 * (lane & 3);
            s[f][0] = (c0g     <= r0g) ? s[f][0] * scale : -CUDART_INF_F;
            s[f][1] = (c0g + 1 <= r0g) ? s[f][1] * scale : -CUDART_INF_F;
            s[f][2] = (c0g     <= r1g) ? s[f][2] * scale : -CUDART_INF_F;
            s[f][3] = (c0g + 1 <= r1g) ? s[f][3] * scale : -CUDART_INF_F;
        }

        // online softmax (rows live in lane groups of 4: shfl_xor 1,2)
        float mx0 = -CUDART_INF_F, mx1 = -CUDART_INF_F;
#pragma unroll
        for (int f = 0; f < 8; f++) {
            mx0 = fmaxf(mx0, fmaxf(s[f][0], s[f][1]));
            mx1 = fmaxf(mx1, fmaxf(s[f][2], s[f][3]));
        }
        mx0 = fmaxf(mx0, __shfl_xor_sync(0xffffffffu, mx0, 1));
        mx0 = fmaxf(mx0, __shfl_xor_sync(0xffffffffu, mx0, 2));
        mx1 = fmaxf(mx1, __shfl_xor_sync(0xffffffffu, mx1, 1));
        mx1 = fmaxf(mx1, __shfl_xor_sync(0xffffffffu, mx1, 2));

        float mn0 = fmaxf(m0, mx0), mn1 = fmaxf(m1, mx1);
        float al0 = __expf(m0 - mn0), al1 = __expf(m1 - mn1);
        m0 = mn0; m1 = mn1;

        float rs0 = 0.f, rs1 = 0.f;
#pragma unroll
        for (int f = 0; f < 8; f++) {
            s[f][0] = __expf(s[f][0] - m0);
            s[f][1] = __expf(s[f][1] - m0);
            s[f][2] = __expf(s[f][2] - m1);
            s[f][3] = __expf(s[f][3] - m1);
            rs0 += s[f][0] + s[f][1];
            rs1 += s[f][2] + s[f][3];
        }
        rs0 += __shfl_xor_sync(0xffffffffu, rs0, 1);
        rs0 += __shfl_xor_sync(0xffffffffu, rs0, 2);
        rs1 += __shfl_xor_sync(0xffffffffu, rs1, 1);
        rs1 += __shfl_xor_sync(0xffffffffu, rs1, 2);
        l0 = l0 * al0 + rs0;
        l1 = l1 * al1 + rs1;

#pragma unroll
        for (int f = 0; f < 16; f++) {
            o[f][0] *= al0; o[f][1] *= al0;
            o[f][2] *= al1; o[f][3] *= al1;
        }

        // P -> Ps (tf32-rounded), warp-private rows
        const int lr0 = 16 * w + (lane >> 2);
#pragma unroll
        for (int f = 0; f < 8; f++) {
            int cc = 8 * f + 2 * (lane & 3);
            *(float2*)(Ps + lr0 * 68 + cc) =
                make_float2(tf32r(s[f][0]), tf32r(s[f][1]));
            *(float2*)(Ps + (lr0 + 8) * 68 + cc) =
                make_float2(tf32r(s[f][2]), tf32r(s[f][3]));
        }
        __syncwarp();

        // O += P V : per warp 16x128
#pragma unroll 2
        for (int kk = 0; kk < 8; kk++) {
            uint32_t a[4];
            ldm4(a, Ps, 16 * w, kk * 8, 68);
#pragma unroll
            for (int j = 0; j < 8; j++) {
                uint32_t b[4];
                ldm4(b, Vt, 16 * j, kk * 8, 68);
                mma8(o[2 * j],     a, b[0], b[2]);
                mma8(o[2 * j + 1], a, b[1], b[3]);
            }
        }
        __syncthreads();
    }

    // epilogue: normalize + tf32-round (ctx feeds the tf32 dense GEMM)
    const float inv0 = 1.f / l0, inv1 = 1.f / l1;
    const int gr0 = q0 + 16 * w + (lane >> 2);
    const int gr1 = gr0 + 8;
#pragma unroll
    for (int f = 0; f < 16; f++) {
        int cc = h * HD + 8 * f + 2 * (lane & 3);
        *(float2*)(g_ctx + (size_t)gr0 * EMB + cc) =
            make_float2(tf32r(o[f][0] * inv0), tf32r(o[f][1] * inv0));
        *(float2*)(g_ctx + (size_t)gr1 * EMB + cc) =
            make_float2(tf32r(o[f][2] * inv1), tf32r(o[f][3] * inv1));
    }
}

// ---------------------------------------------------------------------------
// Launch
// ---------------------------------------------------------------------------
extern "C" void kernel_launch(void* const* d_in, const int* in_sizes, int n_in,
                              void* d_out, int out_size)
{
    const float* x       = (const float*)d_in[0];
    const float* w_qkv   = (const float*)d_in[1];
    const float* w_dense = (const float*)d_in[2];
    float* out = (float*)d_out;

    float *qkv, *ctx, *xr, *wqkvr, *wdr;
    cudaGetSymbolAddress((void**)&qkv,   g_qkv);
    cudaGetSymbolAddress((void**)&ctx,   g_ctx);
    cudaGetSymbolAddress((void**)&xr,    g_xr);
    cudaGetSymbolAddress((void**)&wqkvr, g_wqkvr);
    cudaGetSymbolAddress((void**)&wdr,   g_wdr);

    cudaFuncSetAttribute(gemm_mma, cudaFuncAttributeMaxDynamicSharedMemorySize, GEMM_SMEM);
    cudaFuncSetAttribute(flash_attn_mma, cudaFuncAttributeMaxDynamicSharedMemorySize, ATT_SMEM);

    // 0) tf32-round inputs (removes mma truncation bias)
    round_tf32_kernel<<<512, 256>>>(x,       xr,    S_LEN * EMB / 4);
    round_tf32_kernel<<<512, 256>>>(w_qkv,   wqkvr, FQKV * EMB / 4);
    round_tf32_kernel<<<512, 256>>>(w_dense, wdr,   EMB * EMB / 4);

    // 1) qkv = x @ w_qkv^T   (M=2048, N=3072, K=2048)
    gemm_mma<<<dim3(FQKV / 128, S_LEN / 128), 256, GEMM_SMEM>>>(xr, wqkvr, qkv, S_LEN, FQKV, EMB);
    // 2) RoPE (fp32, in place)
    rope_kernel<<<dim3(S_LEN, NH + NKV), 64>>>();
    // 3) causal GQA flash attention -> ctx (tf32-rounded)
    flash_attn_mma<<<dim3(NH, S_LEN / 128), 256, ATT_SMEM>>>();
    // 4) out = ctx @ w_dense^T  (M=2048, N=2048, K=2048)
    gemm_mma<<<dim3(EMB / 128, S_LEN / 128), 256, GEMM_SMEM>>>(ctx, wdr, out, S_LEN, EMB, EMB);
}

// round 8
// speedup vs baseline: 3.6557x; 1.2222x over previous
#include <cuda_runtime.h>
#include <math_constants.h>
#include <math.h>
#include <cstdint>

// Problem constants
#define S_LEN 2048
#define EMB   2048
#define NH    16
#define NKV   4
#define HD    128
#define FQKV  3072   // NH*HD + 2*NKV*HD

// Scratch (device globals: no allocations allowed)
__device__ float g_qkv[S_LEN * FQKV];     // 25 MB (Q,K tf32-rounded by rope)
__device__ float g_ctx[S_LEN * EMB];      // 17 MB (tf32-rounded ctx)
__device__ float g_xr[S_LEN * EMB];       // 16 MB (tf32-rounded x)
__device__ float g_wqkvr[FQKV * EMB];     // 24 MB
__device__ float g_wdr[EMB * EMB];        // 16 MB
__device__ float g_vt[NKV * HD * S_LEN];  //  4 MB (V transposed, tf32-rounded)

// ---------------------------------------------------------------------------
// Helpers (plain sm_100: mma.sync tensor cores)
// ---------------------------------------------------------------------------
__device__ __forceinline__ uint32_t smem_u32(const void* p) {
    uint32_t a;
    asm("{ .reg .u64 t; cvta.to.shared.u64 t, %1; cvt.u32.u64 %0, t; }"
        : "=r"(a) : "l"(p));
    return a;
}

__device__ __forceinline__ float tf32r(float x) {
    uint32_t u;
    asm("cvt.rna.tf32.f32 %0, %1;" : "=r"(u) : "f"(x));
    return __uint_as_float(u);
}

// D += A(16x8,row) * B(8x8,col)  tf32, f32 accum
__device__ __forceinline__ void mma8(float* c, const uint32_t* a,
                                     uint32_t b0, uint32_t b1) {
    asm volatile(
        "mma.sync.aligned.m16n8k8.row.col.f32.tf32.tf32.f32 "
        "{%0,%1,%2,%3}, {%4,%5,%6,%7}, {%8,%9}, {%0,%1,%2,%3};\n"
        : "+f"(c[0]), "+f"(c[1]), "+f"(c[2]), "+f"(c[3])
        : "r"(a[0]), "r"(a[1]), "r"(a[2]), "r"(a[3]), "r"(b0), "r"(b1));
}

// byte offset of 16B granule (row, g) in an XOR-swizzled tile; gper granules/row
__device__ __forceinline__ uint32_t sw16(int row, int g, int gper) {
    return (uint32_t)(row * gper + (((g ^ row) & 7) | (g & ~7))) * 16;
}

// ldmatrix.x4 from an XOR-swizzled tile (smem byte base), 16-row x 8-f32-col.
__device__ __forceinline__ void ldm4s(uint32_t* r, uint32_t sbase,
                                      int row0, int col0, int gper) {
    int t = threadIdx.x & 31;
    int rr = row0 + (t & 15);
    int gc = (col0 >> 2) + (t >> 4);
    uint32_t addr = sbase + sw16(rr, gc, gper);
    asm volatile("ldmatrix.sync.aligned.m8n8.x4.shared.b16 {%0,%1,%2,%3}, [%4];"
                 : "=r"(r[0]), "=r"(r[1]), "=r"(r[2]), "=r"(r[3]) : "r"(addr));
}

// ldmatrix.x4 from a padded (unswizzled) f32 tile
__device__ __forceinline__ void ldm4(uint32_t* r, const float* base,
                                     int row0, int col0, int stride) {
    int t = threadIdx.x & 31;
    int rr = row0 + (t & 15);
    int cc = col0 + ((t >> 4) << 2);
    uint32_t addr = smem_u32(base + rr * stride + cc);
    asm volatile("ldmatrix.sync.aligned.m8n8.x4.shared.b16 {%0,%1,%2,%3}, [%4];"
                 : "=r"(r[0]), "=r"(r[1]), "=r"(r[2]), "=r"(r[3]) : "r"(addr));
}

__device__ __forceinline__ void cpasync16(uint32_t dst, const float* src) {
    asm volatile("cp.async.cg.shared.global [%0], [%1], 16;" :: "r"(dst), "l"(src));
}
__device__ __forceinline__ void cpcommit() {
    asm volatile("cp.async.commit_group;");
}

// ---------------------------------------------------------------------------
// tf32 pre-round
// ---------------------------------------------------------------------------
__global__ void round_tf32_kernel(const float* __restrict__ in,
                                  float* __restrict__ out, int n4) {
    int i = blockIdx.x * blockDim.x + threadIdx.x;
    for (; i < n4; i += gridDim.x * blockDim.x) {
        float4 v = ((const float4*)in)[i];
        v.x = tf32r(v.x); v.y = tf32r(v.y); v.z = tf32r(v.z); v.w = tf32r(v.w);
        ((float4*)out)[i] = v;
    }
}

// ---------------------------------------------------------------------------
// tf32 mma GEMM: C[m,n] = sum_k A[m,k]*B[n,k]. Block 128x128, BK=32,
// 4 warps (warp tile 64x64: 8 LDSM : 32 HMMA), 2-stage cp.async,
// XOR-swizzled smem (64 KB) -> 3 CTAs/SM, single wave.
// ---------------------------------------------------------------------------
#define GEMM_SMEM 65536   // 2 stages x (A 16KB + B 16KB)

__device__ __forceinline__ void gemm_issue(const float* __restrict__ A,
                                           const float* __restrict__ B,
                                           uint32_t sb, int stage,
                                           int bm, int bn, int K, int k0, int tid) {
    uint32_t as = sb + stage * 32768;
    uint32_t bs = as + 16384;
#pragma unroll
    for (int i = 0; i < 8; i++) {
        int idx = i * 128 + tid;      // 0..1023
        int row = idx >> 3;           // 0..127
        int g   = idx & 7;            // granule (32 f32/row -> 8 granules)
        uint32_t off = sw16(row, g, 8);
        cpasync16(as + off, A + (size_t)(bm + row) * K + k0 + g * 4);
        cpasync16(bs + off, B + (size_t)(bn + row) * K + k0 + g * 4);
    }
    cpcommit();
}

__global__ __launch_bounds__(128, 3) void gemm_mma(const float* __restrict__ A,
                                                   const float* __restrict__ B,
                                                   float* __restrict__ C,
                                                   int M, int N, int K) {
    extern __shared__ float sm[];
    const uint32_t sb = smem_u32(sm);
    const int tid = threadIdx.x;
    const int lane = tid & 31;
    const int wid = tid >> 5;          // 0..3
    const int bm = blockIdx.y * 128;
    const int bn = blockIdx.x * 128;
    const int wm = (wid >> 1) * 64;
    const int wn = (wid & 1) * 64;

    float acc[4][8][4];
#pragma unroll
    for (int i = 0; i < 4; i++)
#pragma unroll
        for (int j = 0; j < 8; j++)
#pragma unroll
            for (int q = 0; q < 4; q++) acc[i][j][q] = 0.f;

    const int NC = K / 32;
    gemm_issue(A, B, sb, 0, bm, bn, K, 0, tid);

    for (int c = 0; c < NC; c++) {
        if (c + 1 < NC) {
            gemm_issue(A, B, sb, (c + 1) & 1, bm, bn, K, (c + 1) * 32, tid);
            asm volatile("cp.async.wait_group 1;");
        } else {
            asm volatile("cp.async.wait_group 0;");
        }
        __syncthreads();

        const uint32_t as = sb + (c & 1) * 32768;
        const uint32_t bs = as + 16384;
#pragma unroll
        for (int kk = 0; kk < 4; kk++) {
            uint32_t a[4][4];
#pragma unroll
            for (int mf = 0; mf < 4; mf++)
                ldm4s(a[mf], as, wm + 16 * mf, kk * 8, 8);
#pragma unroll
            for (int nf = 0; nf < 4; nf++) {
                uint32_t b[4];
                ldm4s(b, bs, wn + 16 * nf, kk * 8, 8);
#pragma unroll
                for (int mf = 0; mf < 4; mf++) {
                    mma8(acc[mf][2 * nf],     a[mf], b[0], b[2]);
                    mma8(acc[mf][2 * nf + 1], a[mf], b[1], b[3]);
                }
            }
        }
        __syncthreads();
    }

#pragma unroll
    for (int mf = 0; mf < 4; mf++) {
        int r0 = bm + wm + mf * 16 + (lane >> 2);
#pragma unroll
        for (int nf = 0; nf < 8; nf++) {
            int cc = bn + wn + nf * 8 + 2 * (lane & 3);
            *(float2*)(C + (size_t)r0 * N + cc) =
                make_float2(acc[mf][nf][0], acc[mf][nf][1]);
            *(float2*)(C + (size_t)(r0 + 8) * N + cc) =
                make_float2(acc[mf][nf][2], acc[mf][nf][3]);
        }
    }
}

// ---------------------------------------------------------------------------
// RoPE in-place on Q,K heads of g_qkv; output tf32-rounded (feeds mma directly)
// ---------------------------------------------------------------------------
__global__ void rope_kernel() {
    int s    = blockIdx.x;
    int head = blockIdx.y;
    int i    = threadIdx.x;

    size_t off = (size_t)s * FQKV +
                 ((head < NH) ? (size_t)head * HD
                              : (size_t)NH * HD + (size_t)(head - NH) * HD);
    float* base = g_qkv + off;

    float inv_freq = expf(-(float)(2 * i) * (9.210340371976184f / 128.f));
    float ang = (float)s * inv_freq;
    float c, sn;
    sincosf(ang, &sn, &c);

    float x1 = base[i];
    float x2 = base[i + 64];
    base[i]      = tf32r(x1 * c - x2 * sn);
    base[i + 64] = tf32r(x2 * c + x1 * sn);
}

// ---------------------------------------------------------------------------
// V transpose: g_vt[kvh*HD + d][s] = tf32r(V[s][kvh][d])
// ---------------------------------------------------------------------------
__global__ void vtrans_kernel() {
    __shared__ float t[32][33];
    int kvh = blockIdx.z;
    int s0 = blockIdx.x * 32, d0 = blockIdx.y * 32;
    int tx = threadIdx.x, ty = threadIdx.y;   // 32 x 8
#pragma unroll
    for (int i = 0; i < 32; i += 8)
        t[ty + i][tx] =
            g_qkv[(size_t)(s0 + ty + i) * FQKV + (NH + NKV) * HD + kvh * HD + d0 + tx];
    __syncthreads();
#pragma unroll
    for (int i = 0; i < 32; i += 8)
        g_vt[((size_t)kvh * HD + d0 + ty + i) * S_LEN + s0 + tx] = tf32r(t[tx][ty + i]);
}

// ---------------------------------------------------------------------------
// Flash attention, mma tf32, fully cp.async-pipelined.
// CTA: 128 q-rows x 1 head, 8 warps (16 q-rows each), k-tile 64.
// smem: Qs 128x128 sw (64K), Ks 2x64x128 sw (64K), Vt 128x64 sw (32K),
//       Ps 128x68 padded (34K) = 198656 B.
// ---------------------------------------------------------------------------
#define AQ_OFF 0
#define AK_OFF 65536
#define AV_OFF 131072
#define AP_F32 40960                 // Ps f32 index base (byte 163840)
#define ATT_SMEM 198656

__global__ __launch_bounds__(256, 1) void flash_attn_mma() {
    extern __shared__ float sm[];
    const uint32_t sb = smem_u32(sm);
    float* Ps = sm + AP_F32;

    const int tid = threadIdx.x;
    const int lane = tid & 31;
    const int w = tid >> 5;
    const int h = blockIdx.x;
    const int kvh = h >> 2;
    const int qt = (int)gridDim.y - 1 - (int)blockIdx.y;  // heavy first
    const int q0 = qt * 128;
    const float scale = 0.08838834764831845f;   // 1/sqrt(128)

    // prologue: Q + K(0) as one commit group
    {
#pragma unroll
        for (int i = 0; i < 16; i++) {
            int idx = i * 256 + tid;
            int row = idx >> 5;
            int g   = idx & 31;
            cpasync16(sb + AQ_OFF + sw16(row, g, 32),
                      g_qkv + (size_t)(q0 + row) * FQKV + h * HD + g * 4);
        }
#pragma unroll
        for (int i = 0; i < 8; i++) {
            int idx = i * 256 + tid;
            int row = idx >> 5;
            int g   = idx & 31;
            cpasync16(sb + AK_OFF + sw16(row, g, 32),
                      g_qkv + (size_t)(row) * FQKV + NH * HD + kvh * HD + g * 4);
        }
        cpcommit();
    }

    float m0 = -CUDART_INF_F, m1 = -CUDART_INF_F, l0 = 0.f, l1 = 0.f;
    float o[16][4];
#pragma unroll
    for (int f = 0; f < 16; f++)
#pragma unroll
        for (int q = 0; q < 4; q++) o[f][q] = 0.f;

    const int nkt = 2 * (qt + 1);
    for (int kt = 0; kt < nkt; kt++) {
        const int k0 = kt * 64;
        __syncthreads();   // prior PV done: Vbuf/Ps safe to overwrite

        // issue V(kt); its latency is hidden by S-mma + softmax
#pragma unroll
        for (int i = 0; i < 8; i++) {
            int idx = i * 256 + tid;
            int row = idx >> 4;          // d 0..127
            int g   = idx & 15;          // 16 granules (64 f32)
            cpasync16(sb + AV_OFF + sw16(row, g, 16),
                      g_vt + ((size_t)(kvh * HD + row)) * S_LEN + k0 + g * 4);
        }
        cpcommit();

        asm volatile("cp.async.wait_group 1;");  // K(kt) (+Q at kt=0) arrived
        __syncthreads();

        // S = Q K^T : per warp 16x64
        const uint32_t ks = sb + AK_OFF + (uint32_t)(kt & 1) * 32768;
        float s[8][4];
#pragma unroll
        for (int f = 0; f < 8; f++)
#pragma unroll
            for (int q = 0; q < 4; q++) s[f][q] = 0.f;

#pragma unroll 4
        for (int kk = 0; kk < 16; kk++) {
            uint32_t a[4];
            ldm4s(a, sb + AQ_OFF, 16 * w, kk * 8, 32);
#pragma unroll
            for (int j = 0; j < 4; j++) {
                uint32_t b[4];
                ldm4s(b, ks, 16 * j, kk * 8, 32);
                mma8(s[2 * j],     a, b[0], b[2]);
                mma8(s[2 * j + 1], a, b[1], b[3]);
            }
        }

        // mask + scale
        const int r0g = q0 + 16 * w + (lane >> 2);
        const int r1g = r0g + 8;
#pragma unroll
        for (int f = 0; f < 8; f++) {
            int c0g = k0 + 8 * f + 2 * (lane & 3);
            s[f][0] = (c0g     <= r0g) ? s[f][0] * scale : -CUDART_INF_F;
            s[f][1] = (c0g + 1 <= r0g) ? s[f][1] * scale : -CUDART_INF_F;
            s[f][2] = (c0g     <= r1g) ? s[f][2] * scale : -CUDART_INF_F;
            s[f][3] = (c0g + 1 <= r1g) ? s[f][3] * scale : -CUDART_INF_F;
        }

        // online softmax
        float mx0 = -CUDART_INF_F, mx1 = -CUDART_INF_F;
#pragma unroll
        for (int f = 0; f < 8; f++) {
            mx0 = fmaxf(mx0, fmaxf(s[f][0], s[f][1]));
            mx1 = fmaxf(mx1, fmaxf(s[f][2], s[f][3]));
        }
        mx0 = fmaxf(mx0, __shfl_xor_sync(0xffffffffu, mx0, 1));
        mx0 = fmaxf(mx0, __shfl_xor_sync(0xffffffffu, mx0, 2));
        mx1 = fmaxf(mx1, __shfl_xor_sync(0xffffffffu, mx1, 1));
        mx1 = fmaxf(mx1, __shfl_xor_sync(0xffffffffu, mx1, 2));

        float mn0 = fmaxf(m0, mx0), mn1 = fmaxf(m1, mx1);
        float al0 = __expf(m0 - mn0), al1 = __expf(m1 - mn1);
        m0 = mn0; m1 = mn1;

        float rs0 = 0.f, rs1 = 0.f;
#pragma unroll
        for (int f = 0; f < 8; f++) {
            s[f][0] = __expf(s[f][0] - m0);
            s[f][1] = __expf(s[f][1] - m0);
            s[f][2] = __expf(s[f][2] - m1);
            s[f][3] = __expf(s[f][3] - m1);
            rs0 += s[f][0] + s[f][1];
            rs1 += s[f][2] + s[f][3];
        }
        rs0 += __shfl_xor_sync(0xffffffffu, rs0, 1);
        rs0 += __shfl_xor_sync(0xffffffffu, rs0, 2);
        rs1 += __shfl_xor_sync(0xffffffffu, rs1, 1);
        rs1 += __shfl_xor_sync(0xffffffffu, rs1, 2);
        l0 = l0 * al0 + rs0;
        l1 = l1 * al1 + rs1;

#pragma unroll
        for (int f = 0; f < 16; f++) {
            o[f][0] *= al0; o[f][1] *= al0;
            o[f][2] *= al1; o[f][3] *= al1;
        }

        // P -> Ps (tf32-rounded), warp-private rows
        const int lr0 = 16 * w + (lane >> 2);
#pragma unroll
        for (int f = 0; f < 8; f++) {
            int cc = 8 * f + 2 * (lane & 3);
            *(float2*)(Ps + lr0 * 68 + cc) =
                make_float2(tf32r(s[f][0]), tf32r(s[f][1]));
            *(float2*)(Ps + (lr0 + 8) * 68 + cc) =
                make_float2(tf32r(s[f][2]), tf32r(s[f][3]));
        }
        __syncwarp();

        // prefetch K(kt+1), then ensure V(kt) arrived
        if (kt + 1 < nkt) {
            const int nk0 = (kt + 1) * 64;
            const uint32_t kd = sb + AK_OFF + (uint32_t)((kt + 1) & 1) * 32768;
#pragma unroll
            for (int i = 0; i < 8; i++) {
                int idx = i * 256 + tid;
                int row = idx >> 5;
                int g   = idx & 31;
                cpasync16(kd + sw16(row, g, 32),
                          g_qkv + (size_t)(nk0 + row) * FQKV + NH * HD + kvh * HD + g * 4);
            }
            cpcommit();
            asm volatile("cp.async.wait_group 1;");   // V(kt) done
        } else {
            asm volatile("cp.async.wait_group 0;");
        }
        __syncthreads();

        // O += P V : per warp 16x128
#pragma unroll 2
        for (int kk = 0; kk < 8; kk++) {
            uint32_t a[4];
            ldm4(a, Ps, 16 * w, kk * 8, 68);
#pragma unroll
            for (int j = 0; j < 8; j++) {
                uint32_t b[4];
                ldm4s(b, sb + AV_OFF, 16 * j, kk * 8, 16);
                mma8(o[2 * j],     a, b[0], b[2]);
                mma8(o[2 * j + 1], a, b[1], b[3]);
            }
        }
    }

    // epilogue: normalize + tf32-round (ctx feeds tf32 dense GEMM)
    const float inv0 = 1.f / l0, inv1 = 1.f / l1;
    const int gr0 = q0 + 16 * w + (lane >> 2);
    const int gr1 = gr0 + 8;
#pragma unroll
    for (int f = 0; f < 16; f++) {
        int cc = h * HD + 8 * f + 2 * (lane & 3);
        *(float2*)(g_ctx + (size_t)gr0 * EMB + cc) =
            make_float2(tf32r(o[f][0] * inv0), tf32r(o[f][1] * inv0));
        *(float2*)(g_ctx + (size_t)gr1 * EMB + cc) =
            make_float2(tf32r(o[f][2] * inv1), tf32r(o[f][3] * inv1));
    }
}

// ---------------------------------------------------------------------------
// Launch
// ---------------------------------------------------------------------------
extern "C" void kernel_launch(void* const* d_in, const int* in_sizes, int n_in,
                              void* d_out, int out_size)
{
    const float* x       = (const float*)d_in[0];
    const float* w_qkv   = (const float*)d_in[1];
    const float* w_dense = (const float*)d_in[2];
    float* out = (float*)d_out;

    float *qkv, *ctx, *xr, *wqkvr, *wdr;
    cudaGetSymbolAddress((void**)&qkv,   g_qkv);
    cudaGetSymbolAddress((void**)&ctx,   g_ctx);
    cudaGetSymbolAddress((void**)&xr,    g_xr);
    cudaGetSymbolAddress((void**)&wqkvr, g_wqkvr);
    cudaGetSymbolAddress((void**)&wdr,   g_wdr);

    cudaFuncSetAttribute(gemm_mma, cudaFuncAttributeMaxDynamicSharedMemorySize, GEMM_SMEM);
    cudaFuncSetAttribute(flash_attn_mma, cudaFuncAttributeMaxDynamicSharedMemorySize, ATT_SMEM);

    // 0) tf32-round inputs
    round_tf32_kernel<<<512, 256>>>(x,       xr,    S_LEN * EMB / 4);
    round_tf32_kernel<<<512, 256>>>(w_qkv,   wqkvr, FQKV * EMB / 4);
    round_tf32_kernel<<<512, 256>>>(w_dense, wdr,   EMB * EMB / 4);

    // 1) qkv = x @ w_qkv^T   (M=2048, N=3072, K=2048)
    gemm_mma<<<dim3(FQKV / 128, S_LEN / 128), 128, GEMM_SMEM>>>(xr, wqkvr, qkv, S_LEN, FQKV, EMB);
    // 2) RoPE (tf32-rounded output)
    rope_kernel<<<dim3(S_LEN, NH + NKV), 64>>>();
    // 3) V transpose + round
    vtrans_kernel<<<dim3(S_LEN / 32, HD / 32, NKV), dim3(32, 8)>>>();
    // 4) causal GQA flash attention -> ctx
    flash_attn_mma<<<dim3(NH, S_LEN / 128), 256, ATT_SMEM>>>();
    // 5) out = ctx @ w_dense^T  (M=2048, N=2048, K=2048)
    gemm_mma<<<dim3(EMB / 128, S_LEN / 128), 128, GEMM_SMEM>>>(ctx, wdr, out, S_LEN, EMB, EMB);
}